// round 2
// baseline (speedup 1.0000x reference)
#include <cuda_runtime.h>

typedef unsigned long long u64;

#define D   64
#define BM  128
#define BN  128
#define PAD 68          // row stride in floats; 68*4=272 B, 16B-aligned
#define MAXROWS 8192

__device__ float g_sq1[MAXROWS];
__device__ float g_sq2[MAXROWS];

// ---------------------------------------------------------------------------
// Row squared-norms: one thread per row, 16x float4 loads.
// ---------------------------------------------------------------------------
__global__ void row_norms_kernel(const float* __restrict__ x, int n, int which) {
    int r = blockIdx.x * blockDim.x + threadIdx.x;
    if (r >= n) return;
    const float4* p = (const float4*)(x + (size_t)r * D);
    float s = 0.f;
#pragma unroll
    for (int i = 0; i < D / 4; ++i) {
        float4 v = p[i];
        s = fmaf(v.x, v.x, s);
        s = fmaf(v.y, v.y, s);
        s = fmaf(v.z, v.z, s);
        s = fmaf(v.w, v.w, s);
    }
    if (which) g_sq2[r] = s; else g_sq1[r] = s;
}

// ---------------------------------------------------------------------------
// Main tile kernel: 128x128 output tile, 256 threads, 8x8 per thread.
// Cross-term via packed fma.rn.f32x2 with K-dimension packing:
//   acc.lo accumulates even-k products, acc.hi odd-k products.
// ---------------------------------------------------------------------------
__global__ __launch_bounds__(256, 1)
void dist_kernel(const float* __restrict__ x1, const float* __restrict__ x2,
                 float* __restrict__ out, int M) {
    extern __shared__ float smem[];
    float* sa = smem;              // [BM][PAD]
    float* sb = smem + BM * PAD;   // [BN][PAD]

    const int n0  = blockIdx.y * BM;
    const int m0  = blockIdx.x * BN;
    const int tid = threadIdx.x;
    const int tx  = tid & 15;      // 16 col-groups of 8
    const int ty  = tid >> 4;      // 16 row-groups of 8

    // ---- tile load: coalesced float4 gmem reads, conflict-free STS ----
    {
        const int c4 = (tid & 15) * 4;   // column quad
        const int rb = tid >> 4;         // row within pass
#pragma unroll
        for (int p = 0; p < 8; ++p) {
            int r = rb + p * 16;
            *(float4*)(sa + r * PAD + c4) =
                *(const float4*)(x1 + (size_t)(n0 + r) * D + c4);
            *(float4*)(sb + r * PAD + c4) =
                *(const float4*)(x2 + (size_t)(m0 + r) * D + c4);
        }
    }
    __syncthreads();

    u64 acc[8][8];
#pragma unroll
    for (int i = 0; i < 8; ++i)
#pragma unroll
        for (int j = 0; j < 8; ++j) acc[i][j] = 0ull;

    // ---- main loop: 4 k-values per iteration (two packed f32x2 pairs) ----
#pragma unroll 4
    for (int k4 = 0; k4 < D / 4; ++k4) {
        ulonglong2 bv[8];
#pragma unroll
        for (int j = 0; j < 8; ++j)
            bv[j] = *(const ulonglong2*)(sb + (tx * 8 + j) * PAD + k4 * 4);
#pragma unroll
        for (int i = 0; i < 8; ++i) {
            ulonglong2 av = *(const ulonglong2*)(sa + (ty * 8 + i) * PAD + k4 * 4);
#pragma unroll
            for (int j = 0; j < 8; ++j) {
                asm("fma.rn.f32x2 %0, %1, %2, %0;"
                    : "+l"(acc[i][j]) : "l"(av.x), "l"(bv[j].x));
                asm("fma.rn.f32x2 %0, %1, %2, %0;"
                    : "+l"(acc[i][j]) : "l"(av.y), "l"(bv[j].y));
            }
        }
    }

    // ---- epilogue: d2 = max(sq1 + sq2 - 2*cross, 0), vectorized stores ----
    float s2v[8];
#pragma unroll
    for (int j = 0; j < 8; ++j) s2v[j] = g_sq2[m0 + tx * 8 + j];

#pragma unroll
    for (int i = 0; i < 8; ++i) {
        float s1 = g_sq1[n0 + ty * 8 + i];
        float res[8];
#pragma unroll
        for (int j = 0; j < 8; ++j) {
            float lo, hi;
            asm("mov.b64 {%0, %1}, %2;" : "=f"(lo), "=f"(hi) : "l"(acc[i][j]));
            float cross = lo + hi;
            res[j] = fmaxf(fmaf(-2.f, cross, s1 + s2v[j]), 0.f);
        }
        float* orow = out + (size_t)(n0 + ty * 8 + i) * M + m0 + tx * 8;
        *(float4*)(orow)     = make_float4(res[0], res[1], res[2], res[3]);
        *(float4*)(orow + 4) = make_float4(res[4], res[5], res[6], res[7]);
    }
}

// ---------------------------------------------------------------------------
extern "C" void kernel_launch(void* const* d_in, const int* in_sizes, int n_in,
                              void* d_out, int out_size) {
    const float* x1 = (const float*)d_in[0];
    const float* x2 = (const float*)d_in[1];
    float* out = (float*)d_out;

    const int N = in_sizes[0] / D;   // 8192
    const int M = in_sizes[1] / D;   // 8192

    const int smem_bytes = (BM + BN) * PAD * sizeof(float);  // 69632
    cudaFuncSetAttribute(dist_kernel,
                         cudaFuncAttributeMaxDynamicSharedMemorySize, smem_bytes);

    row_norms_kernel<<<(N + 255) / 256, 256>>>(x1, N, 0);
    row_norms_kernel<<<(M + 255) / 256, 256>>>(x2, M, 1);

    dim3 grid(M / BN, N / BM);
    dist_kernel<<<grid, 256, smem_bytes>>>(x1, x2, out, M);
}

// round 3
// speedup vs baseline: 2.1776x; 2.1776x over previous
#include <cuda_runtime.h>

typedef unsigned long long u64;

#define D   64
#define BM  128
#define BN  128
#define PAD 68          // row stride in floats; 68 mod 32 == 4 -> conflict-free strided LDS.128
#define MAXROWS 8192

__device__ float g_sq1[MAXROWS];
__device__ float g_sq2[MAXROWS];

// ---------------------------------------------------------------------------
// Row squared-norms: one thread per row, 16x float4 loads.
// ---------------------------------------------------------------------------
__global__ void row_norms_kernel(const float* __restrict__ x, int n, int which) {
    int r = blockIdx.x * blockDim.x + threadIdx.x;
    if (r >= n) return;
    const float4* p = (const float4*)(x + (size_t)r * D);
    float s = 0.f;
#pragma unroll
    for (int i = 0; i < D / 4; ++i) {
        float4 v = p[i];
        s = fmaf(v.x, v.x, s);
        s = fmaf(v.y, v.y, s);
        s = fmaf(v.z, v.z, s);
        s = fmaf(v.w, v.w, s);
    }
    if (which) g_sq2[r] = s; else g_sq1[r] = s;
}

// ---------------------------------------------------------------------------
// Main tile kernel: 128x128 output tile, 256 threads, 8x8 per thread.
// STRIDED thread mapping: thread (tx,ty) owns cols {tx + 16j}, rows {ty + 16i}.
// bv LDS.128 phase: word stride per tx = PAD = 68 === 4 (mod 32)
//   -> thread tx hits bank quad 4*tx..4*tx+3: all 32 banks, zero conflicts.
// av LDS.128: uniform address across the 16 threads sharing ty -> broadcast.
// Cross-term via packed fma.rn.f32x2 (K-pair packing: lo=even k, hi=odd k).
// ---------------------------------------------------------------------------
__global__ __launch_bounds__(256, 1)
void dist_kernel(const float* __restrict__ x1, const float* __restrict__ x2,
                 float* __restrict__ out, int M) {
    extern __shared__ float smem[];
    float* sa = smem;              // [BM][PAD]
    float* sb = smem + BM * PAD;   // [BN][PAD]

    const int n0  = blockIdx.y * BM;
    const int m0  = blockIdx.x * BN;
    const int tid = threadIdx.x;
    const int tx  = tid & 15;      // col lane: cols tx + 16j
    const int ty  = tid >> 4;      // row lane: rows ty + 16i

    // ---- tile load: coalesced float4 gmem reads, conflict-free STS ----
    {
        const int c4 = (tid & 15) * 4;   // column quad
        const int rb = tid >> 4;         // row within pass
#pragma unroll
        for (int p = 0; p < 8; ++p) {
            int r = rb + p * 16;
            *(float4*)(sa + r * PAD + c4) =
                *(const float4*)(x1 + (size_t)(n0 + r) * D + c4);
            *(float4*)(sb + r * PAD + c4) =
                *(const float4*)(x2 + (size_t)(m0 + r) * D + c4);
        }
    }
    __syncthreads();

    u64 acc[8][8];
#pragma unroll
    for (int i = 0; i < 8; ++i)
#pragma unroll
        for (int j = 0; j < 8; ++j) acc[i][j] = 0ull;

    // ---- main loop: 4 k-values per iteration (two packed f32x2 pairs) ----
#pragma unroll 4
    for (int k4 = 0; k4 < D / 4; ++k4) {
        ulonglong2 bv[8];
#pragma unroll
        for (int j = 0; j < 8; ++j)
            bv[j] = *(const ulonglong2*)(sb + (tx + j * 16) * PAD + k4 * 4);
#pragma unroll
        for (int i = 0; i < 8; ++i) {
            ulonglong2 av = *(const ulonglong2*)(sa + (ty + i * 16) * PAD + k4 * 4);
#pragma unroll
            for (int j = 0; j < 8; ++j) {
                asm("fma.rn.f32x2 %0, %1, %2, %0;"
                    : "+l"(acc[i][j]) : "l"(av.x), "l"(bv[j].x));
                asm("fma.rn.f32x2 %0, %1, %2, %0;"
                    : "+l"(acc[i][j]) : "l"(av.y), "l"(bv[j].y));
            }
        }
    }

    // ---- epilogue: d2 = max(sq1 + sq2 - 2*cross, 0) ----
    float s2v[8];
#pragma unroll
    for (int j = 0; j < 8; ++j) s2v[j] = g_sq2[m0 + tx + j * 16];

#pragma unroll
    for (int i = 0; i < 8; ++i) {
        const int row = n0 + ty + i * 16;
        float s1 = g_sq1[row];
        float* orow = out + (size_t)row * M + m0 + tx;
#pragma unroll
        for (int j = 0; j < 8; ++j) {
            float lo, hi;
            asm("mov.b64 {%0, %1}, %2;" : "=f"(lo), "=f"(hi) : "l"(acc[i][j]));
            float cross = lo + hi;
            orow[j * 16] = fmaxf(fmaf(-2.f, cross, s1 + s2v[j]), 0.f);
        }
    }
}

// ---------------------------------------------------------------------------
extern "C" void kernel_launch(void* const* d_in, const int* in_sizes, int n_in,
                              void* d_out, int out_size) {
    const float* x1 = (const float*)d_in[0];
    const float* x2 = (const float*)d_in[1];
    float* out = (float*)d_out;

    const int N = in_sizes[0] / D;   // 8192
    const int M = in_sizes[1] / D;   // 8192

    const int smem_bytes = (BM + BN) * PAD * sizeof(float);  // 69632
    cudaFuncSetAttribute(dist_kernel,
                         cudaFuncAttributeMaxDynamicSharedMemorySize, smem_bytes);

    row_norms_kernel<<<(N + 255) / 256, 256>>>(x1, N, 0);
    row_norms_kernel<<<(M + 255) / 256, 256>>>(x2, M, 1);

    dim3 grid(M / BN, N / BM);
    dist_kernel<<<grid, 256, smem_bytes>>>(x1, x2, out, M);
}

// round 5
// speedup vs baseline: 6.0387x; 2.7731x over previous
#include <cuda_runtime.h>
#include <cstdint>

#define D    64
#define BM   128
#define BN   128
#define PAD  68          // words; 68 mod 32 == 4 -> conflict-free fragment LDS
#define MAXROWS 8192

__device__ float g_sq1[MAXROWS];
__device__ float g_sq2[MAXROWS];

// ---------------------------------------------------------------------------
__global__ void row_norms_kernel(const float* __restrict__ x, int n, int which) {
    int r = blockIdx.x * blockDim.x + threadIdx.x;
    if (r >= n) return;
    const float4* p = (const float4*)(x + (size_t)r * D);
    float s = 0.f;
#pragma unroll
    for (int i = 0; i < D / 4; ++i) {
        float4 v = p[i];
        s = fmaf(v.x, v.x, s); s = fmaf(v.y, v.y, s);
        s = fmaf(v.z, v.z, s); s = fmaf(v.w, v.w, s);
    }
    if (which) g_sq2[r] = s; else g_sq1[r] = s;
}

__device__ __forceinline__ uint32_t f2tf32(float f) {
    uint32_t u;
    asm("cvt.rna.tf32.f32 %0, %1;" : "=r"(u) : "f"(f));
    return u;
}

// ---------------------------------------------------------------------------
// 128x128 tile per CTA, 8 warps (2 x 4), warp tile 64x32.
// cross = x1 . x2^T via mma.sync m16n8k8 tf32 (PTX ISA 7.0, compute_103-legal).
// ---------------------------------------------------------------------------
__global__ __launch_bounds__(256, 2)
void dist_kernel(const float* __restrict__ x1, const float* __restrict__ x2,
                 float* __restrict__ out, int M) {
    extern __shared__ uint32_t smem[];
    uint32_t* sa = smem;              // [BM][PAD] tf32 bits
    uint32_t* sb = smem + BM * PAD;   // [BN][PAD]

    const int n0  = blockIdx.y * BM;
    const int m0  = blockIdx.x * BN;
    const int tid = threadIdx.x;
    const int wid = tid >> 5;
    const int lane = tid & 31;
    const int wm = wid >> 2;          // 0..1 : 64-row band
    const int wn = wid & 3;           // 0..3 : 32-col band
    const int g  = lane >> 2;         // 0..7
    const int q  = lane & 3;          // 0..3

    // ---- stage tiles: gmem float4 -> tf32(RNA) -> smem ----
    {
        const int c4 = (tid & 15) * 4;
        const int rb = tid >> 4;
#pragma unroll
        for (int p = 0; p < 8; ++p) {
            int r = rb + p * 16;
            float4 va = *(const float4*)(x1 + (size_t)(n0 + r) * D + c4);
            float4 vb = *(const float4*)(x2 + (size_t)(m0 + r) * D + c4);
            uint4 ua = make_uint4(f2tf32(va.x), f2tf32(va.y), f2tf32(va.z), f2tf32(va.w));
            uint4 ub = make_uint4(f2tf32(vb.x), f2tf32(vb.y), f2tf32(vb.z), f2tf32(vb.w));
            *(uint4*)(sa + r * PAD + c4) = ua;
            *(uint4*)(sb + r * PAD + c4) = ub;
        }
    }
    __syncthreads();

    float acc[4][4][4];               // [mf][nf][c0..c3]
#pragma unroll
    for (int i = 0; i < 4; ++i)
#pragma unroll
        for (int j = 0; j < 4; ++j)
#pragma unroll
            for (int c = 0; c < 4; ++c) acc[i][j][c] = 0.f;

    // ---- K loop: 8 steps of k=8 ----
#pragma unroll
    for (int ks = 0; ks < 8; ++ks) {
        const int kb = ks * 8;

        // B fragments: b[nf][0..1]; col n = wn*32 + nf*8 + g, k = kb + q (+4)
        uint32_t bfr[4][2];
#pragma unroll
        for (int nf = 0; nf < 4; ++nf) {
            const uint32_t* bp = sb + (wn * 32 + nf * 8 + g) * PAD + kb + q;
            bfr[nf][0] = bp[0];
            bfr[nf][1] = bp[4];
        }

#pragma unroll
        for (int mf = 0; mf < 4; ++mf) {
            const int r = wm * 64 + mf * 16 + g;
            const uint32_t* ap = sa + r * PAD + kb + q;
            uint32_t a0 = ap[0];
            uint32_t a1 = ap[8 * PAD];
            uint32_t a2 = ap[4];
            uint32_t a3 = ap[8 * PAD + 4];
#pragma unroll
            for (int nf = 0; nf < 4; ++nf) {
                asm volatile(
                    "mma.sync.aligned.m16n8k8.row.col.f32.tf32.tf32.f32 "
                    "{%0,%1,%2,%3}, {%4,%5,%6,%7}, {%8,%9}, {%0,%1,%2,%3};"
                    : "+f"(acc[mf][nf][0]), "+f"(acc[mf][nf][1]),
                      "+f"(acc[mf][nf][2]), "+f"(acc[mf][nf][3])
                    : "r"(a0), "r"(a1), "r"(a2), "r"(a3),
                      "r"(bfr[nf][0]), "r"(bfr[nf][1]));
            }
        }
    }

    // ---- epilogue: d2 = max(s1 + s2 - 2*cross, 0) ----
    // c0,c1 -> (row, col), (row, col+1); c2,c3 -> (row+8, ...)
#pragma unroll
    for (int mf = 0; mf < 4; ++mf) {
        const int r_lo = n0 + wm * 64 + mf * 16 + g;
        const float s1a = __ldg(&g_sq1[r_lo]);
        const float s1b = __ldg(&g_sq1[r_lo + 8]);
        float* orow_a = out + (size_t)r_lo * M + m0;
        float* orow_b = orow_a + (size_t)8 * M;
#pragma unroll
        for (int nf = 0; nf < 4; ++nf) {
            const int cidx = wn * 32 + nf * 8 + q * 2;
            const float2 s2 = __ldg((const float2*)&g_sq2[m0 + cidx]);
            float2 ra, rb;
            ra.x = fmaxf(fmaf(-2.f, acc[mf][nf][0], s1a + s2.x), 0.f);
            ra.y = fmaxf(fmaf(-2.f, acc[mf][nf][1], s1a + s2.y), 0.f);
            rb.x = fmaxf(fmaf(-2.f, acc[mf][nf][2], s1b + s2.x), 0.f);
            rb.y = fmaxf(fmaf(-2.f, acc[mf][nf][3], s1b + s2.y), 0.f);
            *(float2*)(orow_a + cidx) = ra;
            *(float2*)(orow_b + cidx) = rb;
        }
    }
}

// ---------------------------------------------------------------------------
extern "C" void kernel_launch(void* const* d_in, const int* in_sizes, int n_in,
                              void* d_out, int out_size) {
    const float* x1 = (const float*)d_in[0];
    const float* x2 = (const float*)d_in[1];
    float* out = (float*)d_out;

    const int N = in_sizes[0] / D;   // 8192
    const int M = in_sizes[1] / D;   // 8192

    const int smem_bytes = 2 * BM * PAD * sizeof(uint32_t);  // 69632
    cudaFuncSetAttribute(dist_kernel,
                         cudaFuncAttributeMaxDynamicSharedMemorySize, smem_bytes);

    row_norms_kernel<<<(N + 255) / 256, 256>>>(x1, N, 0);
    row_norms_kernel<<<(M + 255) / 256, 256>>>(x2, M, 1);

    dim3 grid(M / BN, N / BM);
    dist_kernel<<<grid, 256, smem_bytes>>>(x1, x2, out, M);
}